// round 2
// baseline (speedup 1.0000x reference)
#include <cuda_runtime.h>
#include <math.h>

#define BB 128
#define SS 256
#define LC 16
#define NLAB 9
#define SMALLV (-1000.0f)

// ---------------- scratch (__device__ globals, no allocation) ----------------
__device__ float d_Ef[100*100];            // char_emb @ cWih_f^T + cb_f
__device__ float d_Eb[100*100];            // char_emb @ cWih_b^T + cb_b
__device__ float d_Wiht_f[150*400];        // word Wih_f transposed [k][g]
__device__ float d_Wiht_b[150*400];
__device__ float d_W1t[200*100];           // W1 transposed [k][g]
__device__ float g_char_out[BB*SS*50];
__device__ float g_gpre_f[(size_t)BB*SS*400];
__device__ float g_gpre_b[(size_t)BB*SS*400];
__device__ float g_wh[(size_t)BB*SS*200];
__device__ float g_feats[BB*SS*NLAB];
__device__ float g_perb[BB];

__device__ __forceinline__ float sigmoidf_(float x){ return 1.0f/(1.0f+expf(-x)); }

// ---------------- K0: prep (embedding-projection tables + weight transposes) --
__global__ void prep_kernel(const float* __restrict__ char_emb,
                            const float* __restrict__ cWih_f, const float* __restrict__ cb_f,
                            const float* __restrict__ cWih_b, const float* __restrict__ cb_b,
                            const float* __restrict__ wWih_f, const float* __restrict__ wWih_b,
                            const float* __restrict__ W1)
{
    int tid = blockIdx.x*blockDim.x + threadIdx.x;
    if (tid < 20000) {
        int which = tid / 10000;
        int r = (tid % 10000) / 100;
        int g = tid % 100;
        const float* W  = which ? cWih_b : cWih_f;
        const float* bb = which ? cb_b   : cb_f;
        float acc = bb[g];
        #pragma unroll
        for (int k = 0; k < 25; k++) acc += char_emb[r*25+k] * W[g*25+k];
        (which ? d_Eb : d_Ef)[r*100+g] = acc;
        return;
    }
    int t2 = tid - 20000;
    if (t2 < 120000) {
        int which = t2 / 60000;
        int rem = t2 % 60000;
        int g = rem / 150, k = rem % 150;
        const float* W = which ? wWih_b : wWih_f;
        (which ? d_Wiht_b : d_Wiht_f)[k*400+g] = W[g*150+k];
        return;
    }
    int t3 = t2 - 120000;
    if (t3 < 20000) {
        int g = t3 / 200, k = t3 % 200;
        d_W1t[k*100+g] = W1[g*200+k];
    }
}

// ---------------- K1: char BiLSTM -> g_char_out ------------------------------
// Block owns a batch of sequences; thread g (<100) computes gate row g for both
// directions with Whh rows resident in registers. Input projection comes from
// the precomputed d_Ef/d_Eb tables (vocab is only 100).
__global__ void __launch_bounds__(128) char_lstm_kernel(
    const float* __restrict__ cWhh_f, const float* __restrict__ cWhh_b,
    const int* __restrict__ char_ids, const int* __restrict__ word_num)
{
    int tid = threadIdx.x;
    int g = tid;
    float whf[28], whb[28];
    if (g < 100) {
        #pragma unroll
        for (int k = 0; k < 25; k++) { whf[k]=__ldg(&cWhh_f[g*25+k]); whb[k]=__ldg(&cWhh_b[g*25+k]); }
        #pragma unroll
        for (int k = 25; k < 28; k++) { whf[k]=0.f; whb[k]=0.f; }
    }
    __shared__ __align__(16) float hf[28];
    __shared__ __align__(16) float hb[28];
    __shared__ float sgf[100], sgb[100];
    __shared__ int sid[16];
    __shared__ float smask;

    for (int seq = blockIdx.x; seq < BB*SS; seq += gridDim.x) {
        int b = seq >> 8;
        if (tid < 16) sid[tid] = char_ids[seq*16 + tid];
        if (tid == 0) smask = ((seq & 255) < word_num[b]) ? 1.0f : 0.0f;
        if (tid < 28) { hf[tid] = 0.f; hb[tid] = 0.f; }
        float cf = 0.f, cb = 0.f;
        __syncthreads();
        #pragma unroll 1
        for (int t = 0; t < 16; t++) {
            if (g < 100) {
                float af = __ldg(&d_Ef[sid[t]*100 + g]);
                float ab = __ldg(&d_Eb[sid[15-t]*100 + g]);
                const float4* h4f = (const float4*)hf;
                const float4* h4b = (const float4*)hb;
                #pragma unroll
                for (int k4 = 0; k4 < 7; k4++) {
                    float4 vf = h4f[k4];
                    af += whf[4*k4+0]*vf.x + whf[4*k4+1]*vf.y + whf[4*k4+2]*vf.z + whf[4*k4+3]*vf.w;
                    float4 vb = h4b[k4];
                    ab += whb[4*k4+0]*vb.x + whb[4*k4+1]*vb.y + whb[4*k4+2]*vb.z + whb[4*k4+3]*vb.w;
                }
                sgf[g] = af; sgb[g] = ab;
            }
            __syncthreads();
            if (tid < 25) {
                int j = tid;
                float i_ = sigmoidf_(sgf[j]);
                float f_ = sigmoidf_(sgf[25+j]);
                float gg = tanhf(sgf[50+j]);
                float o_ = sigmoidf_(sgf[75+j]);
                cf = f_*cf + i_*gg;
                hf[j] = o_*tanhf(cf);
            } else if (tid >= 32 && tid < 57) {
                int j = tid - 32;
                float i_ = sigmoidf_(sgb[j]);
                float f_ = sigmoidf_(sgb[25+j]);
                float gg = tanhf(sgb[50+j]);
                float o_ = sigmoidf_(sgb[75+j]);
                cb = f_*cb + i_*gg;
                hb[j] = o_*tanhf(cb);
            }
            __syncthreads();
        }
        if (tid < 25)                    g_char_out[seq*50 + tid]            = hf[tid]*smask;
        else if (tid >= 32 && tid < 57)  g_char_out[seq*50 + 25 + (tid-32)]  = hb[tid-32]*smask;
        __syncthreads();
    }
}

// ---------------- K2: word input projection (GEMM, gathered A) ---------------
// out[row][g] = bias[g] + sum_k A[row][k]*Wih[g][k],
// A[row] = [word_emb[word_ids[row]](100) ; char_out[row](50)].
// Tile: 16 rows x 128 gates per block; thread = 4 gates x 4 rows.
__global__ void __launch_bounds__(128) word_proj_kernel(
    const float* __restrict__ word_emb, const int* __restrict__ word_ids,
    const float* __restrict__ wb_f, const float* __restrict__ wb_b)
{
    int dir = blockIdx.z;
    int rowbase = blockIdx.x * 16;
    int gtile = blockIdx.y * 128;
    int tx = threadIdx.x & 31;
    int ty = threadIdx.x >> 5;

    __shared__ float sA[16*152];
    __shared__ int swid[16];

    if (threadIdx.x < 16) swid[threadIdx.x] = word_ids[rowbase + threadIdx.x];
    __syncthreads();
    for (int idx = threadIdx.x; idx < 16*150; idx += 128) {
        int r = idx / 150, k = idx % 150;
        float v;
        if (k < 100) v = __ldg(&word_emb[(size_t)swid[r]*100 + k]);
        else         v = g_char_out[(rowbase + r)*50 + (k - 100)];
        sA[r*152 + k] = v;
    }
    __syncthreads();

    const float* Wt   = dir ? d_Wiht_b : d_Wiht_f;
    const float* bias = dir ? wb_b : wb_f;
    int gidx[4]; float acc[4][4];
    #pragma unroll
    for (int i = 0; i < 4; i++) {
        gidx[i] = gtile + tx + 32*i;
        float bv = (gidx[i] < 400) ? __ldg(&bias[gidx[i]]) : 0.f;
        #pragma unroll
        for (int j = 0; j < 4; j++) acc[i][j] = bv;
    }
    #pragma unroll 2
    for (int k = 0; k < 150; k++) {
        float w[4];
        #pragma unroll
        for (int i = 0; i < 4; i++)
            w[i] = (gidx[i] < 400) ? __ldg(&Wt[k*400 + gidx[i]]) : 0.f;
        float a[4];
        #pragma unroll
        for (int j = 0; j < 4; j++) a[j] = sA[(ty + 4*j)*152 + k];
        #pragma unroll
        for (int i = 0; i < 4; i++) {
            #pragma unroll
            for (int j = 0; j < 4; j++) acc[i][j] += w[i]*a[j];
        }
    }
    float* out = dir ? g_gpre_b : g_gpre_f;
    #pragma unroll
    for (int j = 0; j < 4; j++) {
        size_t row = (size_t)(rowbase + ty + 4*j);
        #pragma unroll
        for (int i = 0; i < 4; i++)
            if (gidx[i] < 400) out[row*400 + gidx[i]] = acc[i][j];
    }
}

// ---------------- K3: word BiLSTM recurrence ----------------------------------
// One block per (sequence, direction). Thread g (<400) holds Whh[g][0:100] in
// registers; per step only h (25 x LDS.128) is read from shared.
__global__ void __launch_bounds__(416,1) word_rec_kernel(
    const float* __restrict__ wWhh_f, const float* __restrict__ wWhh_b)
{
    int b = blockIdx.x >> 1;
    int dir = blockIdx.x & 1;
    int g = threadIdx.x;
    const float* Whh = dir ? wWhh_b : wWhh_f;
    float w[100];
    if (g < 400) {
        #pragma unroll
        for (int k = 0; k < 100; k++) w[k] = __ldg(&Whh[g*100 + k]);
    }
    __shared__ __align__(16) float sh[100];
    __shared__ float sg[400];
    if (g < 100) sh[g] = 0.f;
    float c = 0.f;
    __syncthreads();
    const float* gpre = dir ? g_gpre_b : g_gpre_f;
    for (int step = 0; step < 256; step++) {
        int t = dir ? (255 - step) : step;
        if (g < 400) {
            float a = gpre[((size_t)(b*256 + t))*400 + g];
            const float4* h4 = (const float4*)sh;
            #pragma unroll
            for (int k4 = 0; k4 < 25; k4++) {
                float4 v = h4[k4];
                a += w[4*k4+0]*v.x + w[4*k4+1]*v.y + w[4*k4+2]*v.z + w[4*k4+3]*v.w;
            }
            sg[g] = a;
        }
        __syncthreads();
        if (g < 100) {
            float i_ = sigmoidf_(sg[g]);
            float f_ = sigmoidf_(sg[100+g]);
            float gg = tanhf(sg[200+g]);
            float o_ = sigmoidf_(sg[300+g]);
            c = f_*c + i_*gg;
            float h = o_*tanhf(c);
            sh[g] = h;
            g_wh[((size_t)(b*256 + t))*200 + dir*100 + g] = h;
        }
        __syncthreads();
    }
}

// ---------------- K4: MLP feats = (tanh(wh@W1^T+b1)@W2^T+b2)*mask -------------
__global__ void __launch_bounds__(128) mlp_kernel(
    const float* __restrict__ b1, const float* __restrict__ W2,
    const float* __restrict__ b2, const int* __restrict__ word_num)
{
    __shared__ float sX[4*200];
    __shared__ float sH[4*104];
    int tid = threadIdx.x;
    for (int grp = blockIdx.x; grp < (BB*SS)/4; grp += gridDim.x) {
        int rowbase = grp*4;
        for (int idx = tid; idx < 800; idx += 128)
            sX[idx] = g_wh[(size_t)rowbase*200 + idx];
        __syncthreads();
        if (tid < 100) {
            float bv = __ldg(&b1[tid]);
            float a0=bv, a1=bv, a2=bv, a3=bv;
            #pragma unroll 4
            for (int k = 0; k < 200; k++) {
                float wv = __ldg(&d_W1t[k*100 + tid]);
                a0 += wv*sX[k]; a1 += wv*sX[200+k]; a2 += wv*sX[400+k]; a3 += wv*sX[600+k];
            }
            sH[tid] = tanhf(a0); sH[104+tid] = tanhf(a1); sH[208+tid] = tanhf(a2); sH[312+tid] = tanhf(a3);
        }
        __syncthreads();
        if (tid < 36) {
            int r = tid / 9, o = tid % 9;
            int row = rowbase + r;
            float acc = __ldg(&b2[o]);
            #pragma unroll 4
            for (int k = 0; k < 100; k++)
                acc += __ldg(&W2[o*100 + k]) * sH[r*104 + k];
            float m = ((row & 255) < word_num[row >> 8]) ? 1.0f : 0.0f;
            g_feats[row*9 + o] = acc * m;
        }
        __syncthreads();
    }
}

// ---------------- K5: CRF numerator + forward algorithm (1 warp / sequence) ---
__global__ void crf_kernel(const float* __restrict__ transition,
                           const int* __restrict__ word_num,
                           const int* __restrict__ label_ids)
{
    int b = blockIdx.x;
    int lane = threadIdx.x;
    __shared__ float sT[121];
    for (int i = lane; i < 121; i += 32) sT[i] = transition[i];
    __syncwarp();
    int wn = word_num[b];
    float alpha = (lane == 9) ? 0.0f : SMALLV;   // start state = 9
    int jj = (lane < 11) ? lane : 0;
    for (int t = 0; t < wn; t++) {
        float obs = (lane < 9) ? g_feats[(size_t)(b*256 + t)*9 + lane] : SMALLV;
        float av[11];
        #pragma unroll
        for (int k = 0; k < 11; k++) av[k] = __shfl_sync(0xffffffffu, alpha, k);
        float mx = -3.0e38f;
        float vv[11];
        #pragma unroll
        for (int k = 0; k < 11; k++) { vv[k] = av[k] + sT[k*11 + jj]; mx = fmaxf(mx, vv[k]); }
        float s = 0.f;
        #pragma unroll
        for (int k = 0; k < 11; k++) s += expf(vv[k] - mx);
        float anew = obs + mx + logf(s);
        alpha = (lane < 11) ? anew : SMALLV;
    }
    float av[11];
    #pragma unroll
    for (int k = 0; k < 11; k++) av[k] = __shfl_sync(0xffffffffu, alpha, k);
    if (lane == 0) {
        // denominator: one more transition into end state 10 (obs contribution 0)
        float mx = -3.0e38f; float vv[11];
        #pragma unroll
        for (int k = 0; k < 11; k++) { vv[k] = av[k] + sT[k*11 + 10]; mx = fmaxf(mx, vv[k]); }
        float s = 0.f;
        #pragma unroll
        for (int k = 0; k < 11; k++) s += expf(vv[k] - mx);
        float denom = mx + logf(s);
        // numerator: gold path score
        float num = 0.f; int prev = 9;
        for (int t = 0; t < wn; t++) {
            int lab = label_ids[b*256 + t];
            num += g_feats[(size_t)(b*256 + t)*9 + lab] + sT[prev*11 + lab];
            prev = lab;
        }
        num += sT[prev*11 + 10];
        g_perb[b] = denom - num;
    }
}

// ---------------- K6: deterministic mean reduction ----------------------------
__global__ void finalize_kernel(float* out)
{
    __shared__ float s[128];
    int tid = threadIdx.x;
    s[tid] = g_perb[tid];
    __syncthreads();
    for (int off = 64; off > 0; off >>= 1) {
        if (tid < off) s[tid] += s[tid + off];
        __syncthreads();
    }
    if (tid == 0) out[0] = s[0] * (1.0f/128.0f);
}

// ---------------- launch -------------------------------------------------------
extern "C" void kernel_launch(void* const* d_in, const int* in_sizes, int n_in,
                              void* d_out, int out_size)
{
    (void)in_sizes; (void)n_in; (void)out_size;
    const float* word_emb   = (const float*)d_in[0];
    const float* char_emb   = (const float*)d_in[1];
    const float* cWih_f     = (const float*)d_in[2];
    const float* cWhh_f     = (const float*)d_in[3];
    const float* cb_f       = (const float*)d_in[4];
    const float* cWih_b     = (const float*)d_in[5];
    const float* cWhh_b     = (const float*)d_in[6];
    const float* cb_b       = (const float*)d_in[7];
    const float* wWih_f     = (const float*)d_in[8];
    const float* wWhh_f     = (const float*)d_in[9];
    const float* wb_f       = (const float*)d_in[10];
    const float* wWih_b     = (const float*)d_in[11];
    const float* wWhh_b     = (const float*)d_in[12];
    const float* wb_b       = (const float*)d_in[13];
    const float* W1         = (const float*)d_in[14];
    const float* b1         = (const float*)d_in[15];
    const float* W2         = (const float*)d_in[16];
    const float* b2         = (const float*)d_in[17];
    const float* transition = (const float*)d_in[18];
    const int*   word_num   = (const int*)d_in[19];
    const int*   word_ids   = (const int*)d_in[20];
    const int*   char_ids   = (const int*)d_in[21];
    const int*   label_ids  = (const int*)d_in[22];

    prep_kernel<<<625, 256>>>(char_emb, cWih_f, cb_f, cWih_b, cb_b, wWih_f, wWih_b, W1);
    char_lstm_kernel<<<2048, 128>>>(cWhh_f, cWhh_b, char_ids, word_num);
    dim3 g2(2048, 4, 2);
    word_proj_kernel<<<g2, 128>>>(word_emb, word_ids, wb_f, wb_b);
    word_rec_kernel<<<256, 416>>>(wWhh_f, wWhh_b);
    mlp_kernel<<<2048, 128>>>(b1, W2, b2, word_num);
    crf_kernel<<<128, 32>>>(transition, word_num, label_ids);
    finalize_kernel<<<1, 128>>>((float*)d_out);
}

// round 3
// speedup vs baseline: 1.2953x; 1.2953x over previous
#include <cuda_runtime.h>
#include <math.h>

#define BB 128
#define SS 256
#define NLAB 9
#define SMALLV (-1000.0f)

// ---------------- scratch (__device__ globals, no allocation) ----------------
__device__ float d_Ef[100*100];            // char_emb @ cWih_f^T + cb_f
__device__ float d_Eb[100*100];            // char_emb @ cWih_b^T + cb_b
__device__ float d_Wiht_f[150*400];        // word Wih_f transposed [k][g]
__device__ float d_Wiht_b[150*400];
__device__ float d_W1t[200*100];           // W1 transposed [k][g]
__device__ float g_char_out[BB*SS*50];
__device__ float g_gpre_f[(size_t)BB*SS*400];
__device__ float g_gpre_b[(size_t)BB*SS*400];
__device__ float g_wh[(size_t)BB*SS*200];
__device__ float g_feats[BB*SS*NLAB];
__device__ float g_perb[BB];

__device__ __forceinline__ float sigmoidf_(float x){ return 1.0f/(1.0f+expf(-x)); }

// ---------------- K0: prep (embedding-projection tables + weight transposes) --
__global__ void prep_kernel(const float* __restrict__ char_emb,
                            const float* __restrict__ cWih_f, const float* __restrict__ cb_f,
                            const float* __restrict__ cWih_b, const float* __restrict__ cb_b,
                            const float* __restrict__ wWih_f, const float* __restrict__ wWih_b,
                            const float* __restrict__ W1)
{
    int tid = blockIdx.x*blockDim.x + threadIdx.x;
    if (tid < 20000) {
        int which = tid / 10000;
        int r = (tid % 10000) / 100;
        int g = tid % 100;
        const float* W  = which ? cWih_b : cWih_f;
        const float* bb = which ? cb_b   : cb_f;
        float acc = bb[g];
        #pragma unroll
        for (int k = 0; k < 25; k++) acc += char_emb[r*25+k] * W[g*25+k];
        (which ? d_Eb : d_Ef)[r*100+g] = acc;
        return;
    }
    int t2 = tid - 20000;
    if (t2 < 120000) {
        int which = t2 / 60000;
        int rem = t2 % 60000;
        int g = rem / 150, k = rem % 150;
        const float* W = which ? wWih_b : wWih_f;
        (which ? d_Wiht_b : d_Wiht_f)[k*400+g] = W[g*150+k];
        return;
    }
    int t3 = t2 - 120000;
    if (t3 < 20000) {
        int g = t3 / 200, k = t3 % 200;
        d_W1t[k*100+g] = W1[g*200+k];
    }
}

// ---------------- K1: char BiLSTM, 2 sequences per block-iteration -------------
// Thread g (<100) computes gate row g for BOTH directions of BOTH sequences
// (4 independent 25-FMA dot chains sharing the register-resident Whh rows).
__global__ void __launch_bounds__(128) char_lstm_kernel(
    const float* __restrict__ cWhh_f, const float* __restrict__ cWhh_b,
    const int* __restrict__ char_ids, const int* __restrict__ word_num)
{
    int tid = threadIdx.x;
    int g = tid;
    float whf[28], whb[28];
    if (g < 100) {
        #pragma unroll
        for (int k = 0; k < 25; k++) { whf[k]=__ldg(&cWhh_f[g*25+k]); whb[k]=__ldg(&cWhh_b[g*25+k]); }
        #pragma unroll
        for (int k = 25; k < 28; k++) { whf[k]=0.f; whb[k]=0.f; }
    }
    __shared__ __align__(16) float hf0[28], hb0[28], hf1[28], hb1[28];
    __shared__ float sgf0[100], sgb0[100], sgf1[100], sgb1[100];
    __shared__ int sid[32];
    __shared__ float smask0, smask1;

    for (int pair = blockIdx.x; pair < (BB*SS)/2; pair += gridDim.x) {
        int seq0 = pair*2, seq1 = pair*2 + 1;
        if (tid < 32) sid[tid] = char_ids[seq0*16 + tid];   // covers both seqs (contiguous)
        if (tid == 0) smask0 = ((seq0 & 255) < word_num[seq0 >> 8]) ? 1.0f : 0.0f;
        if (tid == 1) smask1 = ((seq1 & 255) < word_num[seq1 >> 8]) ? 1.0f : 0.0f;
        if (tid < 28) { hf0[tid]=0.f; hb0[tid]=0.f; hf1[tid]=0.f; hb1[tid]=0.f; }
        float c = 0.f;   // per-thread cell state for the activation role this thread owns
        __syncthreads();
        #pragma unroll 1
        for (int t = 0; t < 16; t++) {
            if (g < 100) {
                float af0 = __ldg(&d_Ef[sid[t]*100 + g]);
                float ab0 = __ldg(&d_Eb[sid[15-t]*100 + g]);
                float af1 = __ldg(&d_Ef[sid[16+t]*100 + g]);
                float ab1 = __ldg(&d_Eb[sid[16+15-t]*100 + g]);
                const float4* f0 = (const float4*)hf0;
                const float4* b0 = (const float4*)hb0;
                const float4* f1 = (const float4*)hf1;
                const float4* b1 = (const float4*)hb1;
                #pragma unroll
                for (int k4 = 0; k4 < 7; k4++) {
                    float4 v;
                    v = f0[k4]; af0 += whf[4*k4]*v.x + whf[4*k4+1]*v.y + whf[4*k4+2]*v.z + whf[4*k4+3]*v.w;
                    v = b0[k4]; ab0 += whb[4*k4]*v.x + whb[4*k4+1]*v.y + whb[4*k4+2]*v.z + whb[4*k4+3]*v.w;
                    v = f1[k4]; af1 += whf[4*k4]*v.x + whf[4*k4+1]*v.y + whf[4*k4+2]*v.z + whf[4*k4+3]*v.w;
                    v = b1[k4]; ab1 += whb[4*k4]*v.x + whb[4*k4+1]*v.y + whb[4*k4+2]*v.z + whb[4*k4+3]*v.w;
                }
                sgf0[g]=af0; sgb0[g]=ab0; sgf1[g]=af1; sgb1[g]=ab1;
            }
            __syncthreads();
            {
                const float* sg = 0; float* hdst = 0; int j = -1;
                if (tid < 25)                      { sg = sgf0; hdst = hf0; j = tid; }
                else if (tid >= 32 && tid < 57)    { sg = sgb0; hdst = hb0; j = tid-32; }
                else if (tid >= 64 && tid < 89)    { sg = sgf1; hdst = hf1; j = tid-64; }
                else if (tid >= 96 && tid < 121)   { sg = sgb1; hdst = hb1; j = tid-96; }
                if (j >= 0) {
                    float i_ = sigmoidf_(sg[j]);
                    float f_ = sigmoidf_(sg[25+j]);
                    float gg = tanhf(sg[50+j]);
                    float o_ = sigmoidf_(sg[75+j]);
                    c = f_*c + i_*gg;
                    hdst[j] = o_*tanhf(c);
                }
            }
            __syncthreads();
        }
        if (tid < 25)                    g_char_out[seq0*50 + tid]          = hf0[tid]*smask0;
        else if (tid >= 32 && tid < 57)  g_char_out[seq0*50 + 25 + tid-32]  = hb0[tid-32]*smask0;
        else if (tid >= 64 && tid < 89)  g_char_out[seq1*50 + tid-64]       = hf1[tid-64]*smask1;
        else if (tid >= 96 && tid < 121) g_char_out[seq1*50 + 25 + tid-96]  = hb1[tid-96]*smask1;
        __syncthreads();
    }
}

// ---------------- K2: word input projection (GEMM, gathered A) ---------------
// 32 rows x 100 gates per block; thread = 4 gates x 8 rows.
__global__ void __launch_bounds__(128) word_proj_kernel(
    const float* __restrict__ word_emb, const int* __restrict__ word_ids,
    const float* __restrict__ wb_f, const float* __restrict__ wb_b)
{
    int dir = blockIdx.z;
    int rowbase = blockIdx.x * 32;
    int gbase = blockIdx.y * 100;
    int tx = threadIdx.x & 31;
    int ty = threadIdx.x >> 5;

    __shared__ float sA[32*152];
    __shared__ int swid[32];

    if (threadIdx.x < 32) swid[threadIdx.x] = word_ids[rowbase + threadIdx.x];
    __syncthreads();
    for (int idx = threadIdx.x; idx < 32*150; idx += 128) {
        int r = idx / 150, k = idx % 150;
        float v;
        if (k < 100) v = __ldg(&word_emb[(size_t)swid[r]*100 + k]);
        else         v = g_char_out[(rowbase + r)*50 + (k - 100)];
        sA[r*152 + k] = v;
    }
    __syncthreads();

    const float* Wt   = dir ? d_Wiht_b : d_Wiht_f;
    const float* bias = dir ? wb_b : wb_f;
    int gidx[4]; bool gok[4]; float acc[4][8];
    #pragma unroll
    for (int i = 0; i < 4; i++) {
        int lg = tx + 32*i;
        gok[i] = (lg < 100);
        gidx[i] = gbase + (gok[i] ? lg : 0);
        float bv = gok[i] ? __ldg(&bias[gidx[i]]) : 0.f;
        #pragma unroll
        for (int j = 0; j < 8; j++) acc[i][j] = bv;
    }
    #pragma unroll 2
    for (int k = 0; k < 150; k++) {
        float w[4];
        #pragma unroll
        for (int i = 0; i < 4; i++) w[i] = __ldg(&Wt[k*400 + gidx[i]]);
        float a[8];
        #pragma unroll
        for (int j = 0; j < 8; j++) a[j] = sA[(ty + 4*j)*152 + k];
        #pragma unroll
        for (int i = 0; i < 4; i++) {
            #pragma unroll
            for (int j = 0; j < 8; j++) acc[i][j] += w[i]*a[j];
        }
    }
    float* out = dir ? g_gpre_b : g_gpre_f;
    #pragma unroll
    for (int j = 0; j < 8; j++) {
        size_t row = (size_t)(rowbase + ty + 4*j);
        #pragma unroll
        for (int i = 0; i < 4; i++)
            if (gok[i]) out[row*400 + gidx[i]] = acc[i][j];
    }
}

// ---------------- K3: word BiLSTM recurrence, 2 sequences per block -----------
// 128 blocks (64 seq-pairs x 2 dirs) = one wave. Thread g (<400) holds
// Whh[g][0:100] in registers and runs TWO independent dot chains (ILP x2),
// with next-step gpre software-prefetched across the barrier.
__global__ void __launch_bounds__(416,1) word_rec_kernel(
    const float* __restrict__ wWhh_f, const float* __restrict__ wWhh_b)
{
    int dir  = blockIdx.x & 1;
    int pair = blockIdx.x >> 1;
    int b0 = pair*2, b1 = pair*2 + 1;
    int g = threadIdx.x;
    const float* Whh = dir ? wWhh_b : wWhh_f;
    float w[100];
    if (g < 400) {
        #pragma unroll
        for (int k = 0; k < 100; k++) w[k] = __ldg(&Whh[g*100 + k]);
    }
    __shared__ __align__(16) float sh0[100], sh1[100];
    __shared__ float sg0[400], sg1[400];
    if (g < 100) { sh0[g] = 0.f; sh1[g] = 0.f; }
    float c = 0.f;
    __syncthreads();
    const float* gpre = dir ? g_gpre_b : g_gpre_f;
    const float* base0 = gpre + (size_t)b0*256*400;
    const float* base1 = gpre + (size_t)b1*256*400;

    int tfirst = dir ? 255 : 0;
    float pf0 = 0.f, pf1 = 0.f;
    if (g < 400) { pf0 = base0[tfirst*400 + g]; pf1 = base1[tfirst*400 + g]; }

    for (int step = 0; step < 256; step++) {
        int t = dir ? (255 - step) : step;
        float a0 = pf0, a1 = pf1;
        if (g < 400 && step < 255) {
            int tn = dir ? (254 - step) : (step + 1);
            pf0 = base0[tn*400 + g];
            pf1 = base1[tn*400 + g];
        }
        if (g < 400) {
            const float4* h40 = (const float4*)sh0;
            const float4* h41 = (const float4*)sh1;
            #pragma unroll
            for (int k4 = 0; k4 < 25; k4++) {
                float4 v0 = h40[k4];
                float4 v1 = h41[k4];
                a0 += w[4*k4]*v0.x + w[4*k4+1]*v0.y + w[4*k4+2]*v0.z + w[4*k4+3]*v0.w;
                a1 += w[4*k4]*v1.x + w[4*k4+1]*v1.y + w[4*k4+2]*v1.z + w[4*k4+3]*v1.w;
            }
            sg0[g] = a0; sg1[g] = a1;
        }
        __syncthreads();
        if (g < 100) {
            float i_ = sigmoidf_(sg0[g]);
            float f_ = sigmoidf_(sg0[100+g]);
            float gg = tanhf(sg0[200+g]);
            float o_ = sigmoidf_(sg0[300+g]);
            c = f_*c + i_*gg;
            float h = o_*tanhf(c);
            sh0[g] = h;
            g_wh[((size_t)(b0*256 + t))*200 + dir*100 + g] = h;
        } else if (g < 200) {
            int j = g - 100;
            float i_ = sigmoidf_(sg1[j]);
            float f_ = sigmoidf_(sg1[100+j]);
            float gg = tanhf(sg1[200+j]);
            float o_ = sigmoidf_(sg1[300+j]);
            c = f_*c + i_*gg;
            float h = o_*tanhf(c);
            sh1[j] = h;
            g_wh[((size_t)(b1*256 + t))*200 + dir*100 + j] = h;
        }
        __syncthreads();
    }
}

// ---------------- K4: MLP feats = (tanh(wh@W1^T+b1)@W2^T+b2)*mask -------------
__global__ void __launch_bounds__(128) mlp_kernel(
    const float* __restrict__ b1, const float* __restrict__ W2,
    const float* __restrict__ b2, const int* __restrict__ word_num)
{
    __shared__ float sX[8*200];
    __shared__ float sH[8*104];
    int tid = threadIdx.x;
    for (int grp = blockIdx.x; grp < (BB*SS)/8; grp += gridDim.x) {
        int rowbase = grp*8;
        for (int idx = tid; idx < 1600; idx += 128)
            sX[idx] = g_wh[(size_t)rowbase*200 + idx];
        __syncthreads();
        if (tid < 100) {
            float bv = __ldg(&b1[tid]);
            float a[8];
            #pragma unroll
            for (int r = 0; r < 8; r++) a[r] = bv;
            #pragma unroll 2
            for (int k = 0; k < 200; k++) {
                float wv = __ldg(&d_W1t[k*100 + tid]);
                #pragma unroll
                for (int r = 0; r < 8; r++) a[r] += wv*sX[r*200 + k];
            }
            #pragma unroll
            for (int r = 0; r < 8; r++) sH[r*104 + tid] = tanhf(a[r]);
        }
        __syncthreads();
        if (tid < 72) {
            int r = tid / 9, o = tid % 9;
            int row = rowbase + r;
            float acc = __ldg(&b2[o]);
            #pragma unroll 4
            for (int k = 0; k < 100; k++)
                acc += __ldg(&W2[o*100 + k]) * sH[r*104 + k];
            float m = ((row & 255) < word_num[row >> 8]) ? 1.0f : 0.0f;
            g_feats[row*9 + o] = acc * m;
        }
        __syncthreads();
    }
}

// ---------------- K5: CRF numerator + forward algorithm (1 warp / sequence) ---
__global__ void crf_kernel(const float* __restrict__ transition,
                           const int* __restrict__ word_num,
                           const int* __restrict__ label_ids)
{
    int b = blockIdx.x;
    int lane = threadIdx.x;
    __shared__ float sT[121];
    for (int i = lane; i < 121; i += 32) sT[i] = transition[i];
    __syncwarp();
    int wn = word_num[b];
    float alpha = (lane == 9) ? 0.0f : SMALLV;   // start state = 9
    int jj = (lane < 11) ? lane : 0;
    for (int t = 0; t < wn; t++) {
        float obs = (lane < 9) ? g_feats[(size_t)(b*256 + t)*9 + lane] : SMALLV;
        float av[11];
        #pragma unroll
        for (int k = 0; k < 11; k++) av[k] = __shfl_sync(0xffffffffu, alpha, k);
        float mx = -3.0e38f;
        float vv[11];
        #pragma unroll
        for (int k = 0; k < 11; k++) { vv[k] = av[k] + sT[k*11 + jj]; mx = fmaxf(mx, vv[k]); }
        float s = 0.f;
        #pragma unroll
        for (int k = 0; k < 11; k++) s += expf(vv[k] - mx);
        float anew = obs + mx + logf(s);
        alpha = (lane < 11) ? anew : SMALLV;
    }
    float av[11];
    #pragma unroll
    for (int k = 0; k < 11; k++) av[k] = __shfl_sync(0xffffffffu, alpha, k);
    if (lane == 0) {
        float mx = -3.0e38f; float vv[11];
        #pragma unroll
        for (int k = 0; k < 11; k++) { vv[k] = av[k] + sT[k*11 + 10]; mx = fmaxf(mx, vv[k]); }
        float s = 0.f;
        #pragma unroll
        for (int k = 0; k < 11; k++) s += expf(vv[k] - mx);
        float denom = mx + logf(s);
        float num = 0.f; int prev = 9;
        for (int t = 0; t < wn; t++) {
            int lab = label_ids[b*256 + t];
            num += g_feats[(size_t)(b*256 + t)*9 + lab] + sT[prev*11 + lab];
            prev = lab;
        }
        num += sT[prev*11 + 10];
        g_perb[b] = denom - num;
    }
}

// ---------------- K6: deterministic mean reduction ----------------------------
__global__ void finalize_kernel(float* out)
{
    __shared__ float s[128];
    int tid = threadIdx.x;
    s[tid] = g_perb[tid];
    __syncthreads();
    for (int off = 64; off > 0; off >>= 1) {
        if (tid < off) s[tid] += s[tid + off];
        __syncthreads();
    }
    if (tid == 0) out[0] = s[0] * (1.0f/128.0f);
}

// ---------------- launch -------------------------------------------------------
extern "C" void kernel_launch(void* const* d_in, const int* in_sizes, int n_in,
                              void* d_out, int out_size)
{
    (void)in_sizes; (void)n_in; (void)out_size;
    const float* word_emb   = (const float*)d_in[0];
    const float* char_emb   = (const float*)d_in[1];
    const float* cWih_f     = (const float*)d_in[2];
    const float* cWhh_f     = (const float*)d_in[3];
    const float* cb_f       = (const float*)d_in[4];
    const float* cWih_b     = (const float*)d_in[5];
    const float* cWhh_b     = (const float*)d_in[6];
    const float* cb_b       = (const float*)d_in[7];
    const float* wWih_f     = (const float*)d_in[8];
    const float* wWhh_f     = (const float*)d_in[9];
    const float* wb_f       = (const float*)d_in[10];
    const float* wWih_b     = (const float*)d_in[11];
    const float* wWhh_b     = (const float*)d_in[12];
    const float* wb_b       = (const float*)d_in[13];
    const float* W1         = (const float*)d_in[14];
    const float* b1         = (const float*)d_in[15];
    const float* W2         = (const float*)d_in[16];
    const float* b2         = (const float*)d_in[17];
    const float* transition = (const float*)d_in[18];
    const int*   word_num   = (const int*)d_in[19];
    const int*   word_ids   = (const int*)d_in[20];
    const int*   char_ids   = (const int*)d_in[21];
    const int*   label_ids  = (const int*)d_in[22];

    prep_kernel<<<625, 256>>>(char_emb, cWih_f, cb_f, cWih_b, cb_b, wWih_f, wWih_b, W1);
    char_lstm_kernel<<<2048, 128>>>(cWhh_f, cWhh_b, char_ids, word_num);
    dim3 g2(1024, 4, 2);
    word_proj_kernel<<<g2, 128>>>(word_emb, word_ids, wb_f, wb_b);
    word_rec_kernel<<<128, 416>>>(wWhh_f, wWhh_b);
    mlp_kernel<<<2048, 128>>>(b1, W2, b2, word_num);
    crf_kernel<<<128, 32>>>(transition, word_num, label_ids);
    finalize_kernel<<<1, 128>>>((float*)d_out);
}